// round 16
// baseline (speedup 1.0000x reference)
#include <cuda_runtime.h>
#include <cstdint>

typedef unsigned long long ull;

// Problem constants
constexpr int B_TOT = 16384;
constexpr int F = 40;
constexpr int D = 32;
constexpr int FD = F * D;              // 1280
constexpr int NB = 16;                 // batches per CTA
constexpr int GRID = B_TOT / NB;       // 1024
constexpr int NTHREADS = 640;          // 20 warps

// Shared strides (floats)
constexpr int HSTR  = 1284;            // h rows       (mod 32 == 4)
constexpr int HOSTR = 1444;            // hout/aggr    (mod 32 == 4; >= 40*36 + 32)
constexpr int GSTR  = 1600;            // g rows (natural)
constexpr int AFS   = 36;              // hout AND aggr f/gi-stride (mod 32 == 4)

// smem offsets (floats)
constexpr int OH  = 0;                     // h:    16*1284 = 20544
constexpr int OHO = OH + NB * HSTR;        // ho:   16*1444 = 23104
constexpr int OG  = OHO + NB * HOSTR;      // g:     8*1600 = 12800
constexpr int OMB = OG + 8 * GSTR;         // mbarriers (3 x u64)
constexpr int SMEM_BYTES = (OMB + 8) * 4;  // 225824 B

// W transpose scratch: [0..40) Wout_t, [40..80) Win_t, each [f][e][d]
__device__ float g_Wt[2 * 40 * 1024];

// ---------------- helpers ----------------
__device__ __forceinline__ ull pack2(float v) {
    ull r;
    asm("mov.b64 %0, {%1, %1};" : "=l"(r) : "f"(v));
    return r;
}
__device__ __forceinline__ ull packf(float lo, float hi) {
    ull r;
    asm("mov.b64 %0, {%1, %2};" : "=l"(r) : "f"(lo), "f"(hi));
    return r;
}
__device__ __forceinline__ ull ffma2(ull a, ull b, ull c) {
    ull d;
    asm("fma.rn.f32x2 %0, %1, %2, %3;" : "=l"(d) : "l"(a), "l"(b), "l"(c));
    return d;
}
__device__ __forceinline__ uint32_t cvt_tf32(float x) {
    uint32_t u;
    asm("cvt.rna.tf32.f32 %0, %1;" : "=r"(u) : "f"(x));
    return u;
}
// D(16x8) += A(16x8,row) * B(8x8,col), tf32 inputs as b32 regs, f32 accum
__device__ __forceinline__ void mma_tf32(float* d,
                                         uint32_t a0, uint32_t a1, uint32_t a2, uint32_t a3,
                                         uint32_t b0, uint32_t b1) {
    asm volatile(
        "mma.sync.aligned.m16n8k8.row.col.f32.tf32.tf32.f32 "
        "{%0,%1,%2,%3}, {%4,%5,%6,%7}, {%8,%9}, {%0,%1,%2,%3};"
        : "+f"(d[0]), "+f"(d[1]), "+f"(d[2]), "+f"(d[3])
        : "r"(a0), "r"(a1), "r"(a2), "r"(a3), "r"(b0), "r"(b1));
}
__device__ __forceinline__ uint32_t smem_u32(const void* p) {
    return (uint32_t)__cvta_generic_to_shared(p);
}
__device__ __forceinline__ void mbar_init(uint32_t mbar, uint32_t cnt) {
    asm volatile("mbarrier.init.shared.b64 [%0], %1;" :: "r"(mbar), "r"(cnt) : "memory");
}
__device__ __forceinline__ void mbar_expect_tx(uint32_t mbar, uint32_t bytes) {
    asm volatile("mbarrier.arrive.expect_tx.shared.b64 _, [%0], %1;"
                 :: "r"(mbar), "r"(bytes) : "memory");
}
__device__ __forceinline__ void mbar_wait(uint32_t mbar, uint32_t parity) {
    uint32_t done;
    asm volatile(
        "{\n\t.reg .pred p;\n\t"
        "mbarrier.try_wait.parity.acquire.cta.shared::cta.b64 p, [%1], %2;\n\t"
        "selp.b32 %0, 1, 0, p;\n\t}"
        : "=r"(done) : "r"(mbar), "r"(parity) : "memory");
    if (!done) {
        asm volatile(
            "{\n\t.reg .pred P1;\n\t"
            "W_%=:\n\t"
            "mbarrier.try_wait.parity.acquire.cta.shared::cta.b64 P1, [%0], %1, 0x989680;\n\t"
            "@P1 bra.uni DONE_%=;\n\t"
            "bra.uni W_%=;\n\t"
            "DONE_%=:\n\t}"
            :: "r"(mbar), "r"(parity) : "memory");
    }
}
__device__ __forceinline__ void bulk_copy(uint32_t dst_smem, const void* src,
                                          uint32_t bytes, uint32_t mbar) {
    asm volatile(
        "cp.async.bulk.shared::cluster.global.mbarrier::complete_tx::bytes "
        "[%0], [%1], %2, [%3];"
        :: "r"(dst_smem), "l"(src), "r"(bytes), "r"(mbar) : "memory");
}

// ---------------- W transpose prologue ----------------
__global__ void __launch_bounds__(1024)
transposeW_kernel(const float* __restrict__ W_in, const float* __restrict__ W_out)
{
    __shared__ float t[32][33];
    const int b = blockIdx.x;                         // 0..79
    const float* src = (b < 40) ? (W_out + b * 1024) : (W_in + (b - 40) * 1024);
    float* dst = g_Wt + b * 1024;
    const int c = threadIdx.x & 31;
    const int r = threadIdx.x >> 5;
    t[r][c] = src[r * 32 + c];       // t[d][e] = W[d][e]
    __syncthreads();
    dst[r * 32 + c] = t[c][r];       // Wt[e][d] = W[d][e]
}

// ---------------- main fused kernel ----------------
__global__ void __launch_bounds__(NTHREADS, 1)
graphlayer_kernel(const float* __restrict__ g,
                  const float* __restrict__ h,
                  const float* __restrict__ bias_p,
                  float* __restrict__ out)
{
    extern __shared__ float smem[];
    float* h_s  = smem + OH;
    float* hoag = smem + OHO;
    float* g_s  = smem + OG;

    const int tid  = threadIdx.x;
    const int lane = tid & 31;
    const int warp = tid >> 5;          // 0..19
    const long b0  = (long)blockIdx.x * NB;

    const uint32_t mb_h  = smem_u32(smem + OMB);
    const uint32_t mb_g1 = mb_h + 8;
    const uint32_t mb_g2 = mb_h + 16;

    if (tid == 0) {
        mbar_init(mb_h, 1);
        mbar_init(mb_g1, 1);
        mbar_init(mb_g2, 1);
    }
    __syncthreads();

    if (tid == 0) {
        mbar_expect_tx(mb_h, NB * FD * 4);
        const uint32_t hdst = smem_u32(h_s);
        #pragma unroll
        for (int j = 0; j < NB; j++)
            bulk_copy(hdst + j * HSTR * 4, h + (b0 + j) * FD, FD * 4, mb_h);
        mbar_expect_tx(mb_g1, 8 * F * F * 4);
        const uint32_t gdst = smem_u32(g_s);
        #pragma unroll
        for (int j = 0; j < 8; j++)
            bulk_copy(gdst + j * GSTR * 4, g + (b0 + j) * (F * F), F * F * 4, mb_g1);
    }

    const float* WoutT = g_Wt;
    const float* WinT  = g_Wt + 40 * 1024;

    const int jg = lane >> 2;           // 0..7 (j rows: jg, jg+8)
    const int dg = lane & 3;            // 0..3 (d-octet: dg*8 .. dg*8+7)

    mbar_wait(mb_h, 0);

    // ---------------- Stage 1: hout[j][gi=f][d] = sum_e Wout[f][d][e] h[j][f][e]
    // 40 field units, exactly 2 per warp. hout stored at gi-stride AFS=36.
    #pragma unroll 1
    for (int f = warp; f < F; f += 20) {
        const float* wt = WoutT + f * 1024 + dg * 8;
        ull acc[2][4] = {};
        #pragma unroll
        for (int e4 = 0; e4 < 8; e4++) {
            float4 hv[2];
            #pragma unroll
            for (int jt = 0; jt < 2; jt++)
                hv[jt] = *(const float4*)&h_s[(jg + 8 * jt) * HSTR + f * 32 + e4 * 4];
            #pragma unroll
            for (int ee = 0; ee < 4; ee++) {
                const ulonglong2 wa = __ldg((const ulonglong2*)(wt + (e4 * 4 + ee) * 32));
                const ulonglong2 wb = __ldg((const ulonglong2*)(wt + (e4 * 4 + ee) * 32 + 4));
                #pragma unroll
                for (int jt = 0; jt < 2; jt++) {
                    const ull xd = pack2(((const float*)&hv[jt])[ee]);
                    acc[jt][0] = ffma2(xd, wa.x, acc[jt][0]);
                    acc[jt][1] = ffma2(xd, wa.y, acc[jt][1]);
                    acc[jt][2] = ffma2(xd, wb.x, acc[jt][2]);
                    acc[jt][3] = ffma2(xd, wb.y, acc[jt][3]);
                }
            }
        }
        #pragma unroll
        for (int jt = 0; jt < 2; jt++) {
            *(ulonglong2*)&hoag[(jg + 8 * jt) * HOSTR + f * AFS + dg * 8] =
                make_ulonglong2(acc[jt][0], acc[jt][1]);
            *(ulonglong2*)&hoag[(jg + 8 * jt) * HOSTR + f * AFS + dg * 8 + 4] =
                make_ulonglong2(acc[jt][2], acc[jt][3]);
        }
    }
    __syncthreads();

    // prefetch g chunk 2 (j = 8..15) into the (now free) h region
    if (tid == 0) {
        mbar_expect_tx(mb_g2, 8 * F * F * 4);
        const uint32_t gdst2 = smem_u32(h_s);
        #pragma unroll
        for (int j = 0; j < 8; j++)
            bulk_copy(gdst2 + j * GSTR * 4, g + (b0 + 8 + j) * (F * F), F * F * 4, mb_g2);
    }

    // ---------------- Stage 2 (tensor): aggr[j] = G[j](40x40) @ HO[j](40x32)
    // warp = batch j. mma m16n8k8 tf32, 3-term split. In place: aggr layout == hout layout.
    if (warp < NB) {
        const int j = warp;
        if (j < 8) mbar_wait(mb_g1, 0);
        else       mbar_wait(mb_g2, 0);
        const float* gj  = (j < 8) ? (g_s + j * GSTR) : (h_s + (j - 8) * GSTR);
        float*       hob = hoag + j * HOSTR;
        const int grp = lane >> 2;      // 0..7
        const int qid = lane & 3;       // 0..3

        float acc[3][4][4] = {};        // [mt][nt][reg]

        #pragma unroll
        for (int kt = 0; kt < 5; kt++) {
            // --- A fragments (g rows), hi/lo tf32 split ---
            uint32_t ah[3][4], al[3][4];
            #pragma unroll
            for (int mt = 0; mt < 3; mt++) {
                const int r0 = mt * 16 + grp;                 // <= 39 always
                int r1 = r0 + 8;
                if (r1 > 39) r1 = 39;                         // clamp (mt==2 garbage rows)
                const int c0 = kt * 8 + qid;
                const float a0 = gj[r0 * F + c0];
                const float a1 = gj[r1 * F + c0];
                const float a2 = gj[r0 * F + c0 + 4];
                const float a3 = gj[r1 * F + c0 + 4];
                ah[mt][0] = cvt_tf32(a0); al[mt][0] = cvt_tf32(a0 - __uint_as_float(ah[mt][0]));
                ah[mt][1] = cvt_tf32(a1); al[mt][1] = cvt_tf32(a1 - __uint_as_float(ah[mt][1]));
                ah[mt][2] = cvt_tf32(a2); al[mt][2] = cvt_tf32(a2 - __uint_as_float(ah[mt][2]));
                ah[mt][3] = cvt_tf32(a3); al[mt][3] = cvt_tf32(a3 - __uint_as_float(ah[mt][3]));
            }
            // --- B fragments (hout), hi/lo split; MMAs ---
            #pragma unroll
            for (int nt = 0; nt < 4; nt++) {
                const int k0 = kt * 8 + qid;
                const int n0 = nt * 8 + grp;
                const float b0 = hob[k0 * AFS + n0];
                const float b1 = hob[(k0 + 4) * AFS + n0];
                const uint32_t bh0 = cvt_tf32(b0);
                const uint32_t bl0 = cvt_tf32(b0 - __uint_as_float(bh0));
                const uint32_t bh1 = cvt_tf32(b1);
                const uint32_t bl1 = cvt_tf32(b1 - __uint_as_float(bh1));
                #pragma unroll
                for (int mt = 0; mt < 3; mt++) {
                    mma_tf32(acc[mt][nt], ah[mt][0], ah[mt][1], ah[mt][2], ah[mt][3], bh0, bh1);
                    mma_tf32(acc[mt][nt], al[mt][0], al[mt][1], al[mt][2], al[mt][3], bh0, bh1);
                    mma_tf32(acc[mt][nt], ah[mt][0], ah[mt][1], ah[mt][2], ah[mt][3], bl0, bl1);
                }
            }
        }
        // --- store aggr in place (all loads done; same f-stride AFS layout) ---
        #pragma unroll
        for (int mt = 0; mt < 3; mt++) {
            const int f0 = mt * 16 + grp;
            const int f1 = f0 + 8;
            #pragma unroll
            for (int nt = 0; nt < 4; nt++) {
                *(ull*)(hob + f0 * AFS + nt * 8 + 2 * qid) =
                    packf(acc[mt][nt][0], acc[mt][nt][1]);
                if (f1 < F)
                    *(ull*)(hob + f1 * AFS + nt * 8 + 2 * qid) =
                        packf(acc[mt][nt][2], acc[mt][nt][3]);
            }
        }
    }
    __syncthreads();

    // ---------------- Stage 3: out[j][f][d] = sum_e Win[f][d][e] aggr[j][f][e] + bias
    const float4 bva = __ldg((const float4*)(bias_p + dg * 8));
    const float4 bvb = __ldg((const float4*)(bias_p + dg * 8 + 4));
    #pragma unroll 1
    for (int f = warp; f < F; f += 20) {
        const float* wt = WinT + f * 1024 + dg * 8;
        ull acc[2][4];
        #pragma unroll
        for (int jt = 0; jt < 2; jt++) {
            acc[jt][0] = packf(bva.x, bva.y);
            acc[jt][1] = packf(bva.z, bva.w);
            acc[jt][2] = packf(bvb.x, bvb.y);
            acc[jt][3] = packf(bvb.z, bvb.w);
        }
        #pragma unroll
        for (int e4 = 0; e4 < 8; e4++) {
            float4 av[2];
            #pragma unroll
            for (int jt = 0; jt < 2; jt++)
                av[jt] = *(const float4*)&hoag[(jg + 8 * jt) * HOSTR + f * AFS + e4 * 4];
            #pragma unroll
            for (int ee = 0; ee < 4; ee++) {
                const ulonglong2 wa = __ldg((const ulonglong2*)(wt + (e4 * 4 + ee) * 32));
                const ulonglong2 wb = __ldg((const ulonglong2*)(wt + (e4 * 4 + ee) * 32 + 4));
                #pragma unroll
                for (int jt = 0; jt < 2; jt++) {
                    const ull xd = pack2(((const float*)&av[jt])[ee]);
                    acc[jt][0] = ffma2(xd, wa.x, acc[jt][0]);
                    acc[jt][1] = ffma2(xd, wa.y, acc[jt][1]);
                    acc[jt][2] = ffma2(xd, wb.x, acc[jt][2]);
                    acc[jt][3] = ffma2(xd, wb.y, acc[jt][3]);
                }
            }
        }
        #pragma unroll
        for (int jt = 0; jt < 2; jt++) {
            const int j = jg + 8 * jt;
            *(ulonglong2*)&out[(b0 + j) * FD + f * 32 + dg * 8] =
                make_ulonglong2(acc[jt][0], acc[jt][1]);
            *(ulonglong2*)&out[(b0 + j) * FD + f * 32 + dg * 8 + 4] =
                make_ulonglong2(acc[jt][2], acc[jt][3]);
        }
    }
}

extern "C" void kernel_launch(void* const* d_in, const int* in_sizes, int n_in,
                              void* d_out, int out_size)
{
    (void)in_sizes; (void)n_in; (void)out_size;
    const float* g     = (const float*)d_in[0];
    const float* h     = (const float*)d_in[1];
    const float* W_in  = (const float*)d_in[2];
    const float* W_out = (const float*)d_in[3];
    const float* bias  = (const float*)d_in[4];
    float* out = (float*)d_out;

    cudaFuncSetAttribute(graphlayer_kernel,
                         cudaFuncAttributeMaxDynamicSharedMemorySize, SMEM_BYTES);

    transposeW_kernel<<<80, 1024>>>(W_in, W_out);
    graphlayer_kernel<<<GRID, NTHREADS, SMEM_BYTES>>>(g, h, bias, out);
}

// round 17
// speedup vs baseline: 1.5849x; 1.5849x over previous
#include <cuda_runtime.h>
#include <cstdint>

typedef unsigned long long ull;

// Problem constants
constexpr int B_TOT = 16384;
constexpr int F = 40;
constexpr int D = 32;
constexpr int FD = F * D;              // 1280
constexpr int NB = 16;                 // batches per CTA
constexpr int GRID = B_TOT / NB;       // 1024
constexpr int NTHREADS = 640;          // 20 warps

// Shared strides (floats)
constexpr int HSTR  = 1284;            // h rows       (mod 32 == 4)
constexpr int HOSTR = 1444;            // hout/aggr    (mod 32 == 4; >= 40*36 + 32)
constexpr int GSTR  = 1600;            // g rows (natural)
constexpr int AFS   = 36;              // hout AND aggr gi/f-stride (mod 32 == 4)

// smem offsets (floats)
constexpr int OH  = 0;                     // h:    16*1284 = 20544
constexpr int OHO = OH + NB * HSTR;        // ho:   16*1444 = 23104
constexpr int OG  = OHO + NB * HOSTR;      // g:     8*1600 = 12800
constexpr int OMB = OG + 8 * GSTR;         // mbarriers (3 x u64)
constexpr int SMEM_BYTES = (OMB + 8) * 4;  // 225824 B

// Fragment-ordered W as bf16 hi/lo for mma.m16n8k16:
// index [(w*40+f)*8 + kt*4+nt][lane] -> uint4(b0h, b1h, b0l, b1l)
__device__ uint4 g_Wb[80 * 8 * 32];        // 327680 B

// ---------------- helpers ----------------
__device__ __forceinline__ ull packf(float lo, float hi) {
    ull r;
    asm("mov.b64 %0, {%1, %2};" : "=l"(r) : "f"(lo), "f"(hi));
    return r;
}
__device__ __forceinline__ uint32_t cvt_tf32(float x) {
    uint32_t u;
    asm("cvt.rna.tf32.f32 %0, %1;" : "=r"(u) : "f"(x));
    return u;
}
// split two f32 into packed bf16x2 hi and bf16x2 lo (lower half = first elem x0)
__device__ __forceinline__ void split_bf(float x0, float x1, uint32_t& hi, uint32_t& lo) {
    asm("cvt.rn.bf16x2.f32 %0, %1, %2;" : "=r"(hi) : "f"(x1), "f"(x0));
    const float h0 = __uint_as_float(hi << 16);
    const float h1 = __uint_as_float(hi & 0xffff0000u);
    const float l0 = x0 - h0;
    const float l1 = x1 - h1;
    asm("cvt.rn.bf16x2.f32 %0, %1, %2;" : "=r"(lo) : "f"(l1), "f"(l0));
}
// D(16x8) += A(16x16,row,bf16) * B(16x8,col,bf16), f32 accum
__device__ __forceinline__ void mma_bf16(float* d, const uint32_t* a,
                                         uint32_t b0, uint32_t b1) {
    asm volatile(
        "mma.sync.aligned.m16n8k16.row.col.f32.bf16.bf16.f32 "
        "{%0,%1,%2,%3}, {%4,%5,%6,%7}, {%8,%9}, {%0,%1,%2,%3};"
        : "+f"(d[0]), "+f"(d[1]), "+f"(d[2]), "+f"(d[3])
        : "r"(a[0]), "r"(a[1]), "r"(a[2]), "r"(a[3]), "r"(b0), "r"(b1));
}
// D(16x8) += A(16x8,row,tf32) * B(8x8,col,tf32), f32 accum  (stage 2)
__device__ __forceinline__ void mma_tf32(float* d,
                                         uint32_t a0, uint32_t a1, uint32_t a2, uint32_t a3,
                                         uint32_t b0, uint32_t b1) {
    asm volatile(
        "mma.sync.aligned.m16n8k8.row.col.f32.tf32.tf32.f32 "
        "{%0,%1,%2,%3}, {%4,%5,%6,%7}, {%8,%9}, {%0,%1,%2,%3};"
        : "+f"(d[0]), "+f"(d[1]), "+f"(d[2]), "+f"(d[3])
        : "r"(a0), "r"(a1), "r"(a2), "r"(a3), "r"(b0), "r"(b1));
}
__device__ __forceinline__ uint32_t smem_u32(const void* p) {
    return (uint32_t)__cvta_generic_to_shared(p);
}
__device__ __forceinline__ void mbar_init(uint32_t mbar, uint32_t cnt) {
    asm volatile("mbarrier.init.shared.b64 [%0], %1;" :: "r"(mbar), "r"(cnt) : "memory");
}
__device__ __forceinline__ void mbar_expect_tx(uint32_t mbar, uint32_t bytes) {
    asm volatile("mbarrier.arrive.expect_tx.shared.b64 _, [%0], %1;"
                 :: "r"(mbar), "r"(bytes) : "memory");
}
__device__ __forceinline__ void mbar_wait(uint32_t mbar, uint32_t parity) {
    uint32_t done;
    asm volatile(
        "{\n\t.reg .pred p;\n\t"
        "mbarrier.try_wait.parity.acquire.cta.shared::cta.b64 p, [%1], %2;\n\t"
        "selp.b32 %0, 1, 0, p;\n\t}"
        : "=r"(done) : "r"(mbar), "r"(parity) : "memory");
    if (!done) {
        asm volatile(
            "{\n\t.reg .pred P1;\n\t"
            "W_%=:\n\t"
            "mbarrier.try_wait.parity.acquire.cta.shared::cta.b64 P1, [%0], %1, 0x989680;\n\t"
            "@P1 bra.uni DONE_%=;\n\t"
            "bra.uni W_%=;\n\t"
            "DONE_%=:\n\t}"
            :: "r"(mbar), "r"(parity) : "memory");
    }
}
__device__ __forceinline__ void bulk_copy(uint32_t dst_smem, const void* src,
                                          uint32_t bytes, uint32_t mbar) {
    asm volatile(
        "cp.async.bulk.shared::cluster.global.mbarrier::complete_tx::bytes "
        "[%0], [%1], %2, [%3];"
        :: "r"(dst_smem), "l"(src), "r"(bytes), "r"(mbar) : "memory");
}

// ---------------- W fragment-build prologue (bf16 hi/lo, m16n8k16 B layout) --
// block = (w, f); thread = (kt, nt, lane).
// B element: col d = nt*8 + (lane>>2); rows e = kt*16 + (lane&3)*2 (+1) for b0,
// rows +8 for b1. Value = W[f][d][e].
__global__ void __launch_bounds__(256)
buildWfrag_kernel(const float* __restrict__ W_in, const float* __restrict__ W_out)
{
    const int blk = blockIdx.x;             // 0..79 == w*40 + f
    const int w = blk / 40;                 // 0 = Wout (stage1), 1 = Win (stage3)
    const int f = blk % 40;
    const float* src = (w == 0) ? W_out : W_in;

    const int t    = threadIdx.x;
    const int kt   = t >> 7;                // 0..1
    const int nt   = (t >> 5) & 3;          // 0..3
    const int lane = t & 31;
    const int gq   = lane >> 2;
    const int tg   = lane & 3;

    const int d  = nt * 8 + gq;
    const int e0 = kt * 16 + 2 * tg;
    const float* row = src + f * 1024 + d * 32;
    uint32_t b0h, b0l, b1h, b1l;
    split_bf(row[e0],     row[e0 + 1], b0h, b0l);
    split_bf(row[e0 + 8], row[e0 + 9], b1h, b1l);
    g_Wb[blk * 256 + (kt * 4 + nt) * 32 + lane] = make_uint4(b0h, b1h, b0l, b1l);
}

// ---------------- main fused kernel ----------------
__global__ void __launch_bounds__(NTHREADS, 1)
graphlayer_kernel(const float* __restrict__ g,
                  const float* __restrict__ h,
                  const float* __restrict__ bias_p,
                  float* __restrict__ out)
{
    extern __shared__ float smem[];
    float* h_s  = smem + OH;
    float* hoag = smem + OHO;
    float* g_s  = smem + OG;

    const int tid  = threadIdx.x;
    const int lane = tid & 31;
    const int warp = tid >> 5;          // 0..19
    const long b0  = (long)blockIdx.x * NB;

    const uint32_t mb_h  = smem_u32(smem + OMB);
    const uint32_t mb_g1 = mb_h + 8;
    const uint32_t mb_g2 = mb_h + 16;

    if (tid == 0) {
        mbar_init(mb_h, 1);
        mbar_init(mb_g1, 1);
        mbar_init(mb_g2, 1);
    }
    __syncthreads();

    if (tid == 0) {
        mbar_expect_tx(mb_h, NB * FD * 4);
        const uint32_t hdst = smem_u32(h_s);
        #pragma unroll
        for (int j = 0; j < NB; j++)
            bulk_copy(hdst + j * HSTR * 4, h + (b0 + j) * FD, FD * 4, mb_h);
        mbar_expect_tx(mb_g1, 8 * F * F * 4);
        const uint32_t gdst = smem_u32(g_s);
        #pragma unroll
        for (int j = 0; j < 8; j++)
            bulk_copy(gdst + j * GSTR * 4, g + (b0 + j) * (F * F), F * F * 4, mb_g1);
    }

    const int gq = lane >> 2;           // 0..7
    const int tg = lane & 3;            // 0..3

    mbar_wait(mb_h, 0);

    // ---------------- Stage 1 (bf16 tensor): hout[j][gi=f][d] = h[j][f][:] @ Wout[f]^T
    // One warp per field (2 fields/warp). D[16j x 32d] = A[16x32] @ B[32x32].
    #pragma unroll 2
    for (int f = warp; f < F; f += 20) {
        const uint4* wb = g_Wb + f * 256 + lane;        // stage-1 frags (w=0)
        float acc[4][4] = {};
        #pragma unroll
        for (int kt = 0; kt < 2; kt++) {
            const float* ap = h_s + f * 32 + kt * 16 + 2 * tg;
            uint32_t ah[4], al[4];
            {
                const float2 x0 = *(const float2*)(ap + gq * HSTR);
                const float2 x1 = *(const float2*)(ap + (gq + 8) * HSTR);
                const float2 x2 = *(const float2*)(ap + gq * HSTR + 8);
                const float2 x3 = *(const float2*)(ap + (gq + 8) * HSTR + 8);
                split_bf(x0.x, x0.y, ah[0], al[0]);
                split_bf(x1.x, x1.y, ah[1], al[1]);
                split_bf(x2.x, x2.y, ah[2], al[2]);
                split_bf(x3.x, x3.y, ah[3], al[3]);
            }
            #pragma unroll
            for (int nt = 0; nt < 4; nt++) {
                const uint4 w = __ldg(wb + (kt * 4 + nt) * 32);
                mma_bf16(acc[nt], ah, w.x, w.y);   // Ah*Bh
                mma_bf16(acc[nt], al, w.x, w.y);   // Al*Bh
                mma_bf16(acc[nt], ah, w.z, w.w);   // Ah*Bl
            }
        }
        #pragma unroll
        for (int nt = 0; nt < 4; nt++) {
            *(ull*)&hoag[gq * HOSTR + f * AFS + nt * 8 + 2 * tg] =
                packf(acc[nt][0], acc[nt][1]);
            *(ull*)&hoag[(gq + 8) * HOSTR + f * AFS + nt * 8 + 2 * tg] =
                packf(acc[nt][2], acc[nt][3]);
        }
    }
    __syncthreads();

    // prefetch g chunk 2 (j = 8..15) into the (now free) h region
    if (tid == 0) {
        mbar_expect_tx(mb_g2, 8 * F * F * 4);
        const uint32_t gdst2 = smem_u32(h_s);
        #pragma unroll
        for (int j = 0; j < 8; j++)
            bulk_copy(gdst2 + j * GSTR * 4, g + (b0 + 8 + j) * (F * F), F * F * 4, mb_g2);
    }

    // ---------------- Stage 2 (tf32 tensor, validated): aggr[j] = G[j](40x40) @ HO[j](40x32)
    if (warp < NB) {
        const int j = warp;
        if (j < 8) mbar_wait(mb_g1, 0);
        else       mbar_wait(mb_g2, 0);
        const float* gj  = (j < 8) ? (g_s + j * GSTR) : (h_s + (j - 8) * GSTR);
        float*       hob = hoag + j * HOSTR;
        const int grp = lane >> 2;      // 0..7
        const int qid = lane & 3;       // 0..3

        float acc[3][4][4] = {};        // [mt][nt][reg]

        #pragma unroll
        for (int kt = 0; kt < 5; kt++) {
            uint32_t ah[3][4], al[3][4];
            #pragma unroll
            for (int mt = 0; mt < 3; mt++) {
                const int r0 = mt * 16 + grp;
                int r1 = r0 + 8;
                if (r1 > 39) r1 = 39;                 // clamp (mt==2 garbage rows)
                const int c0 = kt * 8 + qid;
                const float a0 = gj[r0 * F + c0];
                const float a1 = gj[r1 * F + c0];
                const float a2 = gj[r0 * F + c0 + 4];
                const float a3 = gj[r1 * F + c0 + 4];
                ah[mt][0] = cvt_tf32(a0); al[mt][0] = cvt_tf32(a0 - __uint_as_float(ah[mt][0]));
                ah[mt][1] = cvt_tf32(a1); al[mt][1] = cvt_tf32(a1 - __uint_as_float(ah[mt][1]));
                ah[mt][2] = cvt_tf32(a2); al[mt][2] = cvt_tf32(a2 - __uint_as_float(ah[mt][2]));
                ah[mt][3] = cvt_tf32(a3); al[mt][3] = cvt_tf32(a3 - __uint_as_float(ah[mt][3]));
            }
            #pragma unroll
            for (int nt = 0; nt < 4; nt++) {
                const int k0 = kt * 8 + qid;
                const int n0 = nt * 8 + grp;
                const float b0v = hob[k0 * AFS + n0];
                const float b1v = hob[(k0 + 4) * AFS + n0];
                const uint32_t bh0 = cvt_tf32(b0v);
                const uint32_t bl0 = cvt_tf32(b0v - __uint_as_float(bh0));
                const uint32_t bh1 = cvt_tf32(b1v);
                const uint32_t bl1 = cvt_tf32(b1v - __uint_as_float(bh1));
                #pragma unroll
                for (int mt = 0; mt < 3; mt++) {
                    mma_tf32(acc[mt][nt], ah[mt][0], ah[mt][1], ah[mt][2], ah[mt][3], bh0, bh1);
                    mma_tf32(acc[mt][nt], al[mt][0], al[mt][1], al[mt][2], al[mt][3], bh0, bh1);
                    mma_tf32(acc[mt][nt], ah[mt][0], ah[mt][1], ah[mt][2], ah[mt][3], bl0, bl1);
                }
            }
        }
        // store aggr in place (all loads done; same AFS layout)
        #pragma unroll
        for (int mt = 0; mt < 3; mt++) {
            const int f0 = mt * 16 + grp;
            const int f1 = f0 + 8;
            #pragma unroll
            for (int nt = 0; nt < 4; nt++) {
                *(ull*)(hob + f0 * AFS + nt * 8 + 2 * qid) =
                    packf(acc[mt][nt][0], acc[mt][nt][1]);
                if (f1 < F)
                    *(ull*)(hob + f1 * AFS + nt * 8 + 2 * qid) =
                        packf(acc[mt][nt][2], acc[mt][nt][3]);
            }
        }
    }
    __syncthreads();

    // ---------------- Stage 3 (bf16 tensor): out[j][f][:] = aggr[j][f][:] @ Win[f]^T + bias
    float2 bias2[4];
    #pragma unroll
    for (int nt = 0; nt < 4; nt++)
        bias2[nt] = __ldg((const float2*)(bias_p + nt * 8 + 2 * tg));

    #pragma unroll 2
    for (int f = warp; f < F; f += 20) {
        const uint4* wb = g_Wb + (40 + f) * 256 + lane;   // stage-3 frags (w=1)
        float acc[4][4] = {};
        #pragma unroll
        for (int kt = 0; kt < 2; kt++) {
            const float* ap = hoag + f * AFS + kt * 16 + 2 * tg;
            uint32_t ah[4], al[4];
            {
                const float2 x0 = *(const float2*)(ap + gq * HOSTR);
                const float2 x1 = *(const float2*)(ap + (gq + 8) * HOSTR);
                const float2 x2 = *(const float2*)(ap + gq * HOSTR + 8);
                const float2 x3 = *(const float2*)(ap + (gq + 8) * HOSTR + 8);
                split_bf(x0.x, x0.y, ah[0], al[0]);
                split_bf(x1.x, x1.y, ah[1], al[1]);
                split_bf(x2.x, x2.y, ah[2], al[2]);
                split_bf(x3.x, x3.y, ah[3], al[3]);
            }
            #pragma unroll
            for (int nt = 0; nt < 4; nt++) {
                const uint4 w = __ldg(wb + (kt * 4 + nt) * 32);
                mma_bf16(acc[nt], ah, w.x, w.y);
                mma_bf16(acc[nt], al, w.x, w.y);
                mma_bf16(acc[nt], ah, w.z, w.w);
            }
        }
        #pragma unroll
        for (int nt = 0; nt < 4; nt++) {
            *(ull*)&out[(b0 + gq) * FD + f * 32 + nt * 8 + 2 * tg] =
                packf(acc[nt][0] + bias2[nt].x, acc[nt][1] + bias2[nt].y);
            *(ull*)&out[(b0 + gq + 8) * FD + f * 32 + nt * 8 + 2 * tg] =
                packf(acc[nt][2] + bias2[nt].x, acc[nt][3] + bias2[nt].y);
        }
    }
}

extern "C" void kernel_launch(void* const* d_in, const int* in_sizes, int n_in,
                              void* d_out, int out_size)
{
    (void)in_sizes; (void)n_in; (void)out_size;
    const float* g     = (const float*)d_in[0];
    const float* h     = (const float*)d_in[1];
    const float* W_in  = (const float*)d_in[2];
    const float* W_out = (const float*)d_in[3];
    const float* bias  = (const float*)d_in[4];
    float* out = (float*)d_out;

    cudaFuncSetAttribute(graphlayer_kernel,
                         cudaFuncAttributeMaxDynamicSharedMemorySize, SMEM_BYTES);

    buildWfrag_kernel<<<80, 256>>>(W_in, W_out);
    graphlayer_kernel<<<GRID, NTHREADS, SMEM_BYTES>>>(g, h, bias, out);
}